// round 13
// baseline (speedup 1.0000x reference)
#include <cuda_runtime.h>
#include <cuda_bf16.h>
#include <math.h>
#include <stdint.h>

// ---------------------------------------------------------------------------
// Problem constants
// ---------------------------------------------------------------------------
#define S_   256
#define LA_  128
#define LB_  512
#define DQ_  256
#define DKV_ 265
#define DQK_ 512
#define DV_  512
#define KPAD 272            // DKV_ padded to multiple of 16 (16B-aligned rows)

#define ROWS_A (S_ * LA_)   // 32768
#define ROWS_B (S_ * LB_)   // 131072

// Scratch (device globals; zero-initialized at load; no allocation allowed)
__device__ __align__(16) float g_Yq [(size_t)ROWS_A * DQK_];
__device__ __align__(16) float g_Yk [(size_t)ROWS_B * DQK_];
__device__ __align__(16) float g_Yv [(size_t)ROWS_B * DV_];
__device__ __align__(16) float g_Ywv[(size_t)ROWS_A * DV_];
__device__ __align__(16) float g_Yf [(size_t)ROWS_A * DQ_];
__device__ __align__(16) float g_Bp  [(size_t)ROWS_B * KPAD];
__device__ __align__(16) float g_Wkvp[1024 * KPAD];          // Wk rows 0-511, Wv rows 512-1023
__device__ float g_stats[8 * 512];
__device__ float g_cnt[2];

// ---------------------------------------------------------------------------
// Helpers
// ---------------------------------------------------------------------------
__device__ __forceinline__ void split2(float x0, float x1, uint32_t& h, uint32_t& l) {
    uint32_t hp;
    asm("cvt.rn.bf16x2.f32 %0, %1, %2;" : "=r"(hp) : "f"(x1), "f"(x0));
    float h0 = __uint_as_float(hp << 16);
    float h1 = __uint_as_float(hp & 0xffff0000u);
    asm("cvt.rn.bf16x2.f32 %0, %1, %2;" : "=r"(l) : "f"(x1 - h1), "f"(x0 - h0));
    h = hp;
}

#define MMA_BF16(c, a, b)                                                  \
  asm volatile("mma.sync.aligned.m16n8k16.row.col.f32.bf16.bf16.f32 "      \
    "{%0,%1,%2,%3}, {%4,%5,%6,%7}, {%8,%9}, {%0,%1,%2,%3};"                \
    : "+f"(c[0]), "+f"(c[1]), "+f"(c[2]), "+f"(c[3])                       \
    : "r"(a[0]), "r"(a[1]), "r"(a[2]), "r"(a[3]), "r"(b[0]), "r"(b[1]))

#define CP_ASYNC16(smem_a, gptr) \
  asm volatile("cp.async.cg.shared.global [%0], [%1], 16;" :: "r"(smem_a), "l"(gptr))
#define CP_COMMIT() asm volatile("cp.async.commit_group;")
#define CP_WAIT0()  asm volatile("cp.async.wait_group 0;" ::: "memory")

// ---------------------------------------------------------------------------
// Fused init: zero stats + length sums. One block, 256 threads.
// ---------------------------------------------------------------------------
__global__ void init_kernel(const int* __restrict__ a_lens,
                            const int* __restrict__ b_lens) {
    int t = threadIdx.x;
    for (int i = t; i < 8 * 512; i += 256) g_stats[i] = 0.0f;

    __shared__ int sh[256];
    sh[t] = a_lens[t];
    __syncthreads();
    for (int o = 128; o; o >>= 1) { if (t < o) sh[t] += sh[t + o]; __syncthreads(); }
    if (t == 0) g_cnt[0] = (float)sh[0];
    __syncthreads();
    sh[t] = b_lens[t];
    __syncthreads();
    for (int o = 128; o; o >>= 1) { if (t < o) sh[t] += sh[t + o]; __syncthreads(); }
    if (t == 0) g_cnt[1] = (float)sh[0];
}

// ---------------------------------------------------------------------------
// Fused pad: B (valid rows only) -> Bp; Wk, Wv -> fused Wkvp.
// ---------------------------------------------------------------------------
__global__ void pad_all_kernel(const float* __restrict__ B,
                               const float* __restrict__ Wk,
                               const float* __restrict__ Wv,
                               const int* __restrict__ b_lens) {
    int bid = blockIdx.x;
    const float* src;
    float* dst;
    if (bid < ROWS_B) {
        int sidx = bid >> 9;
        if ((bid & 511) >= b_lens[sidx]) return;   // invalid row: Bp stays 0
        src = B + (size_t)bid * DKV_;
        dst = g_Bp + (size_t)bid * KPAD;
    } else if (bid < ROWS_B + 512) {
        int r = bid - ROWS_B;
        src = Wk + (size_t)r * DKV_;
        dst = g_Wkvp + (size_t)r * KPAD;
    } else {
        int r = bid - ROWS_B - 512;
        src = Wv + (size_t)r * DKV_;
        dst = g_Wkvp + (size_t)(r + 512) * KPAD;
    }
    for (int k = threadIdx.x; k < KPAD; k += blockDim.x)
        dst[k] = (k < DKV_) ? src[k] : 0.0f;
}

// ---------------------------------------------------------------------------
// Tensor-core GEMM: bf16 split, cp.async double buffer, one sync per k-iter,
// fused masked BN stats, invalid row-tile skip, dual-output (fused KV) mode:
//   blocks with col >= N write the second output/bias/stat set.
// 256 threads = 8 warps (2m x 4n), warp tile 64x32, block tile 128x128.
// ---------------------------------------------------------------------------
#define TBK 16
#define TST 24

__global__ __launch_bounds__(256)
void gemm_tc(const float* __restrict__ X, const float* __restrict__ W,
             const float* __restrict__ bias, float* __restrict__ C,
             const float* __restrict__ bias2, float* __restrict__ C2,
             int M, int N, int K,
             const int* __restrict__ lens, int Lshift,
             float* __restrict__ sumOut, float* __restrict__ sqOut,
             float* __restrict__ sum2,  float* __restrict__ sq2) {
    __shared__ float Xs[2][128][TST];
    __shared__ float Ws[2][128][TST];

    size_t row0 = (size_t)blockIdx.y * 128;
    int Lm1 = (1 << Lshift) - 1;
    if (((int)(row0 & Lm1)) >= lens[row0 >> Lshift]) return;

    int tid  = threadIdx.x;
    int warp = tid >> 5, lane = tid & 31;
    int wm = warp >> 2;
    int wn = warp & 3;
    int g  = lane >> 2, tig = lane & 3;

    int wcol0 = blockIdx.x * 128;     // column in fused weight space
    int col0  = wcol0;
    const float* bias_ = bias;
    float* C_ = C;
    float* sum_ = sumOut;
    float* sq_  = sqOut;
    if (col0 >= N) {                   // second output set (fused KV mode)
        col0 -= N;
        bias_ = bias2; C_ = C2; sum_ = sum2; sq_ = sq2;
    }

    float c[4][4][4];
#pragma unroll
    for (int mt = 0; mt < 4; mt++)
#pragma unroll
        for (int nt = 0; nt < 4; nt++)
#pragma unroll
            for (int i = 0; i < 4; i++) c[mt][nt][i] = 0.0f;

    int xr = tid >> 1;
    int xk = (tid & 1) * 8;

    const float* Xp = X + (row0 + xr) * (size_t)K + xk;
    const float* Wp = W + (size_t)(wcol0 + xr) * K + xk;

    uint32_t sx[2] = { (uint32_t)__cvta_generic_to_shared(&Xs[0][xr][xk]),
                       (uint32_t)__cvta_generic_to_shared(&Xs[1][xr][xk]) };
    uint32_t sw[2] = { (uint32_t)__cvta_generic_to_shared(&Ws[0][xr][xk]),
                       (uint32_t)__cvta_generic_to_shared(&Ws[1][xr][xk]) };

    int nk = K / TBK;

    auto stage = [&](int i, int b) {
        int k0 = i * TBK;
        CP_ASYNC16(sx[b],      Xp + k0);
        CP_ASYNC16(sx[b] + 16, Xp + k0 + 4);
        CP_ASYNC16(sw[b],      Wp + k0);
        CP_ASYNC16(sw[b] + 16, Wp + k0 + 4);
        CP_COMMIT();
    };

    stage(0, 0);

    for (int i = 0; i < nk; i++) {
        int buf = i & 1;
        CP_WAIT0();
        __syncthreads();
        if (i + 1 < nk) stage(i + 1, buf ^ 1);

        uint32_t ah[4][4], al[4][4];
#pragma unroll
        for (int mt = 0; mt < 4; mt++) {
            int r = wm * 64 + mt * 16 + g;
            float2 p0 = *reinterpret_cast<const float2*>(&Xs[buf][r][2 * tig]);
            float2 p1 = *reinterpret_cast<const float2*>(&Xs[buf][r + 8][2 * tig]);
            float2 p2 = *reinterpret_cast<const float2*>(&Xs[buf][r][2 * tig + 8]);
            float2 p3 = *reinterpret_cast<const float2*>(&Xs[buf][r + 8][2 * tig + 8]);
            split2(p0.x, p0.y, ah[mt][0], al[mt][0]);
            split2(p1.x, p1.y, ah[mt][1], al[mt][1]);
            split2(p2.x, p2.y, ah[mt][2], al[mt][2]);
            split2(p3.x, p3.y, ah[mt][3], al[mt][3]);
        }
#pragma unroll
        for (int nt = 0; nt < 4; nt++) {
            int n = wn * 32 + nt * 8 + g;
            float2 q0 = *reinterpret_cast<const float2*>(&Ws[buf][n][2 * tig]);
            float2 q1 = *reinterpret_cast<const float2*>(&Ws[buf][n][2 * tig + 8]);
            uint32_t bh[2], bl[2];
            split2(q0.x, q0.y, bh[0], bl[0]);
            split2(q1.x, q1.y, bh[1], bl[1]);
#pragma unroll
            for (int mt = 0; mt < 4; mt++) {
                MMA_BF16(c[mt][nt], ah[mt], bh);
                MMA_BF16(c[mt][nt], ah[mt], bl);
                MMA_BF16(c[mt][nt], al[mt], bh);
            }
        }
    }

    float ssum[4][2], ssq[4][2];
#pragma unroll
    for (int nt = 0; nt < 4; nt++) {
        ssum[nt][0] = ssum[nt][1] = 0.0f;
        ssq[nt][0]  = ssq[nt][1]  = 0.0f;
    }

#pragma unroll
    for (int mt = 0; mt < 4; mt++) {
        size_t r0 = row0 + wm * 64 + mt * 16 + g;
        size_t r1 = r0 + 8;
        bool v0 = ((int)(r0 & Lm1)) < lens[r0 >> Lshift];
        bool v1 = ((int)(r1 & Lm1)) < lens[r1 >> Lshift];
#pragma unroll
        for (int nt = 0; nt < 4; nt++) {
            int cc = col0 + wn * 32 + nt * 8 + tig * 2;
            float b0 = bias_[cc], b1 = bias_[cc + 1];
            float y00 = c[mt][nt][0] + b0;
            float y01 = c[mt][nt][1] + b1;
            float y10 = c[mt][nt][2] + b0;
            float y11 = c[mt][nt][3] + b1;
            C_[r0 * N + cc]     = y00;
            C_[r0 * N + cc + 1] = y01;
            C_[r1 * N + cc]     = y10;
            C_[r1 * N + cc + 1] = y11;
            if (v0) {
                ssum[nt][0] += y00; ssq[nt][0] += y00 * y00;
                ssum[nt][1] += y01; ssq[nt][1] += y01 * y01;
            }
            if (v1) {
                ssum[nt][0] += y10; ssq[nt][0] += y10 * y10;
                ssum[nt][1] += y11; ssq[nt][1] += y11 * y11;
            }
        }
    }

#pragma unroll
    for (int o = 16; o >= 4; o >>= 1) {
#pragma unroll
        for (int nt = 0; nt < 4; nt++) {
#pragma unroll
            for (int j = 0; j < 2; j++) {
                ssum[nt][j] += __shfl_xor_sync(0xffffffffu, ssum[nt][j], o);
                ssq[nt][j]  += __shfl_xor_sync(0xffffffffu, ssq[nt][j],  o);
            }
        }
    }
    if (g == 0) {
#pragma unroll
        for (int nt = 0; nt < 4; nt++) {
            int cc = col0 + wn * 32 + nt * 8 + tig * 2;
#pragma unroll
            for (int j = 0; j < 2; j++) {
                atomicAdd(&sum_[cc + j], ssum[nt][j]);
                atomicAdd(&sq_[cc + j],  ssq[nt][j]);
            }
        }
    }
}

// ---------------------------------------------------------------------------
// BN apply + ReLU + optional L2 row-normalize + optional row mask.
// 256 threads, two rows per block; invalid rows skipped / zeroed.
// ---------------------------------------------------------------------------
__global__ __launch_bounds__(256)
void bn_apply_kernel(float* __restrict__ Y, int D,
                     const float* __restrict__ ssum, const float* __restrict__ ssq,
                     const float* __restrict__ cntp,
                     const float* __restrict__ gamma, const float* __restrict__ beta,
                     const int* __restrict__ lens, int L,
                     int normalize, int maskOut, float* __restrict__ out) {
    int t  = threadIdx.x;
    int tl = t & 127;
    int r  = blockIdx.x * 2 + (t >> 7);
    int sidx = r / L;
    bool valid = ((r - sidx * L) < lens[sidx]);
    float inv = 1.0f / (*cntp);
    int active = D >> 2;

    float z[4] = {0.0f, 0.0f, 0.0f, 0.0f};
    float ss = 0.0f;
    if (tl < active && valid) {
        int cc = tl * 4;
        float4 y = *reinterpret_cast<const float4*>(&Y[(size_t)r * D + cc]);
        float yv[4] = {y.x, y.y, y.z, y.w};
#pragma unroll
        for (int i = 0; i < 4; i++) {
            int ci = cc + i;
            float mean = ssum[ci] * inv;
            float var  = fmaxf(ssq[ci] * inv - mean * mean, 0.0f);
            float zz = (yv[i] - mean) * rsqrtf(var + 1e-5f) * gamma[ci] + beta[ci];
            zz = fmaxf(zz, 0.0f);
            z[i] = zz;
            ss += zz * zz;
        }
    }

    __shared__ float red[8];
#pragma unroll
    for (int o = 16; o; o >>= 1) ss += __shfl_xor_sync(0xffffffffu, ss, o);
    if ((t & 31) == 0) red[t >> 5] = ss;
    __syncthreads();
    int rg = (t >> 7) * 4;
    float tot = red[rg] + red[rg + 1] + red[rg + 2] + red[rg + 3];

    float scale = 1.0f;
    if (normalize) scale = 1.0f / fmaxf(sqrtf(tot), 1e-12f);

    if (tl < active) {
        float* dst = out ? out : Y;
        if (valid) {
            *reinterpret_cast<float4*>(&dst[(size_t)r * D + tl * 4]) =
                make_float4(z[0] * scale, z[1] * scale, z[2] * scale, z[3] * scale);
        } else if (maskOut) {
            *reinterpret_cast<float4*>(&dst[(size_t)r * D + tl * 4]) =
                make_float4(0.0f, 0.0f, 0.0f, 0.0f);
        }
    }
}

// ---------------------------------------------------------------------------
// Tensor-core attention v3: 32 q-rows / block, 256 threads (8 warps,
// warp tile 16x128), single-buffered staging, 110KB smem -> 2 blocks/SM.
// ---------------------------------------------------------------------------
#define AST 520
#define KBST 20
#define ATT_SMEM_FLOATS (32 * AST + 512 * KBST + 32 * KBST)   // 27520
#define ATT_SMEM_BYTES  (ATT_SMEM_FLOATS * 4)                 // 110080

__global__ __launch_bounds__(256)
void attention_tc(const float* __restrict__ q, const float* __restrict__ k,
                  const float* __restrict__ v, const int* __restrict__ b_lens,
                  const int* __restrict__ a_lens, float* __restrict__ wv) {
    int s   = blockIdx.x;
    int a0  = blockIdx.y * 32;
    if (a0 >= a_lens[s]) return;

    extern __shared__ float sm[];
    float* sS = sm;                    // [32][AST]
    float* sK = sm + 32 * AST;         // [512][KBST]
    float* sQ = sK + 512 * KBST;       // [32][KBST]

    int tid = threadIdx.x;
    int warp = tid >> 5, lane = tid & 31;
    int wm = warp >> 2;                // 0..1 (m16 tile)
    int wn = warp & 3;                 // 0..3 (n128 slice)
    int g  = lane >> 2, tig = lane & 3;
    int nb = b_lens[s];
    int nb16 = (nb + 15) & ~15;
    int nbc  = nb16 >> 4;

    const float* qs = q + ((size_t)s * LA_ + a0) * DQK_;
    const float* ks = k + (size_t)s * LB_ * DQK_;
    const float* vs = v + (size_t)s * LB_ * DV_;

    uint32_t sKa = (uint32_t)__cvta_generic_to_shared(sK);
    uint32_t sQa = (uint32_t)__cvta_generic_to_shared(sQ);

    float c[16][4];
#pragma unroll
    for (int nt = 0; nt < 16; nt++)
#pragma unroll
        for (int i = 0; i < 4; i++) c[nt][i] = 0.0f;

    int r0 = wm * 16 + g;              // fragment rows r0, r0+8

    // ---------------- Phase A: S = Q K^T (single-buffered d-chunks) --------
    for (int ci = 0; ci < 32; ci++) {
        int d0 = ci * 16;
        if (tid < 128) {
            int r = tid >> 2, c4 = (tid & 3) * 4;
            CP_ASYNC16(sQa + (r * KBST + c4) * 4,
                       qs + (size_t)r * DQK_ + d0 + c4);
        }
#pragma unroll
        for (int j = 0; j < 8; j++) {
            int idx = tid + 256 * j;
            int r = idx >> 2, c4 = (idx & 3) * 4;
            if (r < nb16)
                CP_ASYNC16(sKa + (r * KBST + c4) * 4,
                           ks + (size_t)r * DQK_ + d0 + c4);
        }
        CP_COMMIT();
        CP_WAIT0();
        __syncthreads();

        if (wn * 128 < nb) {
            uint32_t ah[4], al[4];
            float2 p0 = *reinterpret_cast<const float2*>(&sQ[r0 * KBST + 2 * tig]);
            float2 p1 = *reinterpret_cast<const float2*>(&sQ[(r0 + 8) * KBST + 2 * tig]);
            float2 p2 = *reinterpret_cast<const float2*>(&sQ[r0 * KBST + 2 * tig + 8]);
            float2 p3 = *reinterpret_cast<const float2*>(&sQ[(r0 + 8) * KBST + 2 * tig + 8]);
            split2(p0.x, p0.y, ah[0], al[0]);
            split2(p1.x, p1.y, ah[1], al[1]);
            split2(p2.x, p2.y, ah[2], al[2]);
            split2(p3.x, p3.y, ah[3], al[3]);
#pragma unroll
            for (int nt = 0; nt < 16; nt++) {
                int nbase = wn * 128 + nt * 8;
                if (nbase < nb) {
                    int n = nbase + g;
                    float2 q0 = *reinterpret_cast<const float2*>(&sK[n * KBST + 2 * tig]);
                    float2 q1 = *reinterpret_cast<const float2*>(&sK[n * KBST + 2 * tig + 8]);
                    uint32_t bh[2], bl[2];
                    split2(q0.x, q0.y, bh[0], bl[0]);
                    split2(q1.x, q1.y, bh[1], bl[1]);
                    MMA_BF16(c[nt], ah, bh);
                    MMA_BF16(c[nt], ah, bl);
                    MMA_BF16(c[nt], al, bh);
                }
            }
        }
        __syncthreads();
    }

    // scale + mask -> sS
    const float scaler = 6.25f;
#pragma unroll
    for (int nt = 0; nt < 16; nt++) {
        int col = wn * 128 + nt * 8 + tig * 2;
        float v0 = c[nt][0] * scaler;
        float v1 = c[nt][1] * scaler;
        float v2 = c[nt][2] * scaler;
        float v3 = c[nt][3] * scaler;
        sS[r0 * AST + col]           = (col     < nb) ? v0 : -1e30f;
        sS[r0 * AST + col + 1]       = (col + 1 < nb) ? v1 : -1e30f;
        sS[(r0 + 8) * AST + col]     = (col     < nb) ? v2 : -1e30f;
        sS[(r0 + 8) * AST + col + 1] = (col + 1 < nb) ? v3 : -1e30f;
    }
    __syncthreads();

    // softmax: warp per 4 rows, bounded to nb16
#pragma unroll
    for (int rr = 0; rr < 4; rr++) {
        int row = warp * 4 + rr;
        float m = -1e30f;
        for (int cc = lane; cc < nb16; cc += 32) m = fmaxf(m, sS[row * AST + cc]);
#pragma unroll
        for (int o = 16; o; o >>= 1) m = fmaxf(m, __shfl_xor_sync(0xffffffffu, m, o));
        float sum = 0.0f;
        for (int cc = lane; cc < nb16; cc += 32) {
            float e = __expf(sS[row * AST + cc] - m);
            sS[row * AST + cc] = e;
            sum += e;
        }
#pragma unroll
        for (int o = 16; o; o >>= 1) sum += __shfl_xor_sync(0xffffffffu, sum, o);
        float invs = 1.0f / sum;
        for (int cc = lane; cc < nb16; cc += 32) sS[row * AST + cc] *= invs;
    }
    __syncthreads();

    // ---------------- Phase B: WV = P V (chunks bounded by nbc) ------------
#pragma unroll
    for (int nt = 0; nt < 16; nt++)
#pragma unroll
        for (int i = 0; i < 4; i++) c[nt][i] = 0.0f;

    for (int bi = 0; bi < nbc; bi++) {
        int b0 = bi * 16;
        // stage V^T chunk [512 dv][16 b]
#pragma unroll
        for (int j = 0; j < 8; j++) {
            int idx = tid + 256 * j;
            int kk = idx & 15, dg = idx >> 4;
            float4 vv = *reinterpret_cast<const float4*>(
                &vs[(size_t)(b0 + kk) * DV_ + dg * 4]);
            sK[(dg * 4 + 0) * KBST + kk] = vv.x;
            sK[(dg * 4 + 1) * KBST + kk] = vv.y;
            sK[(dg * 4 + 2) * KBST + kk] = vv.z;
            sK[(dg * 4 + 3) * KBST + kk] = vv.w;
        }
        __syncthreads();

        uint32_t ah[4], al[4];
        float2 p0 = *reinterpret_cast<const float2*>(&sS[r0 * AST + b0 + 2 * tig]);
        float2 p1 = *reinterpret_cast<const float2*>(&sS[(r0 + 8) * AST + b0 + 2 * tig]);
        float2 p2 = *reinterpret_cast<const float2*>(&sS[r0 * AST + b0 + 2 * tig + 8]);
        float2 p3 = *reinterpret_cast<const float2*>(&sS[(r0 + 8) * AST + b0 + 2 * tig + 8]);
        split2(p0.x, p0.y, ah[0], al[0]);
        split2(p1.x, p1.y, ah[1], al[1]);
        split2(p2.x, p2.y, ah[2], al[2]);
        split2(p3.x, p3.y, ah[3], al[3]);
#pragma unroll
        for (int nt = 0; nt < 16; nt++) {
            int n = wn * 128 + nt * 8 + g;
            float2 q0 = *reinterpret_cast<const float2*>(&sK[n * KBST + 2 * tig]);
            float2 q1 = *reinterpret_cast<const float2*>(&sK[n * KBST + 2 * tig + 8]);
            uint32_t bh[2], bl[2];
            split2(q0.x, q0.y, bh[0], bl[0]);
            split2(q1.x, q1.y, bh[1], bl[1]);
            MMA_BF16(c[nt], ah, bh);
            MMA_BF16(c[nt], ah, bl);
            MMA_BF16(c[nt], al, bh);
        }
        __syncthreads();
    }

    float* wvp = wv + ((size_t)s * LA_ + a0) * DV_;
#pragma unroll
    for (int nt = 0; nt < 16; nt++) {
        int col = wn * 128 + nt * 8 + tig * 2;
        wvp[(size_t)r0 * DV_ + col]           = c[nt][0];
        wvp[(size_t)r0 * DV_ + col + 1]       = c[nt][1];
        wvp[(size_t)(r0 + 8) * DV_ + col]     = c[nt][2];
        wvp[(size_t)(r0 + 8) * DV_ + col + 1] = c[nt][3];
    }
}

// ---------------------------------------------------------------------------
// Launch
// ---------------------------------------------------------------------------
extern "C" void kernel_launch(void* const* d_in, const int* in_sizes, int n_in,
                              void* d_out, int out_size) {
    const float* A      = (const float*)d_in[0];
    const float* B      = (const float*)d_in[1];
    const int*   a_lens = (const int*)  d_in[2];
    const int*   b_lens = (const int*)  d_in[3];
    const float* Wq     = (const float*)d_in[4];
    const float* bq     = (const float*)d_in[5];
    const float* gq     = (const float*)d_in[6];
    const float* betaq  = (const float*)d_in[7];
    const float* Wk     = (const float*)d_in[8];
    const float* bk     = (const float*)d_in[9];
    const float* gk     = (const float*)d_in[10];
    const float* betak  = (const float*)d_in[11];
    const float* Wv     = (const float*)d_in[12];
    const float* bv     = (const float*)d_in[13];
    const float* gv     = (const float*)d_in[14];
    const float* betav  = (const float*)d_in[15];
    const float* Wf     = (const float*)d_in[16];
    const float* bf     = (const float*)d_in[17];
    const float* gf     = (const float*)d_in[18];
    const float* betaf  = (const float*)d_in[19];
    float* out = (float*)d_out;

    float *Yq, *Yk, *Yv, *Ywv, *Yf, *Bp, *Wkvp, *stats, *cnt;
    cudaGetSymbolAddress((void**)&Yq,   g_Yq);
    cudaGetSymbolAddress((void**)&Yk,   g_Yk);
    cudaGetSymbolAddress((void**)&Yv,   g_Yv);
    cudaGetSymbolAddress((void**)&Ywv,  g_Ywv);
    cudaGetSymbolAddress((void**)&Yf,   g_Yf);
    cudaGetSymbolAddress((void**)&Bp,   g_Bp);
    cudaGetSymbolAddress((void**)&Wkvp, g_Wkvp);
    cudaGetSymbolAddress((void**)&stats, g_stats);
    cudaGetSymbolAddress((void**)&cnt,  g_cnt);

    cudaFuncSetAttribute(attention_tc,
                         cudaFuncAttributeMaxDynamicSharedMemorySize, ATT_SMEM_BYTES);

    float* sum_q = stats + 0 * 512;
    float* sq_q  = stats + 1 * 512;
    float* sum_k = stats + 2 * 512;
    float* sq_k  = stats + 3 * 512;
    float* sum_v = stats + 4 * 512;
    float* sq_v  = stats + 5 * 512;
    float* sum_f = stats + 6 * 512;
    float* sq_f  = stats + 7 * 512;

    // 0) fused init + fused pad
    init_kernel<<<1, 256>>>(a_lens, b_lens);
    pad_all_kernel<<<ROWS_B + 1024, 128>>>(B, Wk, Wv, b_lens);

    // 1) Q projection + fused K/V projection
    gemm_tc<<<dim3(DQK_ / 128, ROWS_A / 128), 256>>>(A, Wq, bq, Yq, bq, Yq,
        ROWS_A, DQK_, DQ_, a_lens, 7, sum_q, sq_q, sum_q, sq_q);
    gemm_tc<<<dim3(8, ROWS_B / 128), 256>>>(Bp, Wkvp, bk, Yk, bv, Yv,
        ROWS_B, DQK_, KPAD, b_lens, 9, sum_k, sq_k, sum_v, sq_v);

    // 2) BN + ReLU + L2-normalize (in-place)
    bn_apply_kernel<<<ROWS_A / 2, 256>>>(Yq, DQK_, sum_q, sq_q, cnt + 0, gq, betaq,
                                         a_lens, LA_, 1, 0, nullptr);
    bn_apply_kernel<<<ROWS_B / 2, 256>>>(Yk, DQK_, sum_k, sq_k, cnt + 1, gk, betak,
                                         b_lens, LB_, 1, 0, nullptr);
    bn_apply_kernel<<<ROWS_B / 2, 256>>>(Yv, DV_,  sum_v, sq_v, cnt + 1, gv, betav,
                                         b_lens, LB_, 1, 0, nullptr);

    // 3) attention (32-row tiles, 2 blocks/SM)
    attention_tc<<<dim3(S_, LA_ / 32), 256, ATT_SMEM_BYTES>>>(
        Yq, Yk, Yv, b_lens, a_lens, Ywv);

    // 4) final projection + BN + ReLU + output mask
    gemm_tc<<<dim3(DQ_ / 128, ROWS_A / 128), 256>>>(Ywv, Wf, bf, Yf, bf, Yf,
        ROWS_A, DQ_, DV_, a_lens, 7, sum_f, sq_f, sum_f, sq_f);
    bn_apply_kernel<<<ROWS_A / 2, 256>>>(Yf, DQ_, sum_f, sq_f, cnt + 0, gf, betaf,
                                         a_lens, LA_, 0, 1, out);
}

// round 14
// speedup vs baseline: 1.0512x; 1.0512x over previous
#include <cuda_runtime.h>
#include <cuda_bf16.h>
#include <math.h>
#include <stdint.h>

// ---------------------------------------------------------------------------
// Problem constants
// ---------------------------------------------------------------------------
#define S_   256
#define LA_  128
#define LB_  512
#define DQ_  256
#define DKV_ 265
#define DQK_ 512
#define DV_  512
#define KPAD 272            // DKV_ padded to multiple of 16 (16B-aligned rows)

#define ROWS_A (S_ * LA_)   // 32768
#define ROWS_B (S_ * LB_)   // 131072

// Scratch (device globals; zero-initialized at load; no allocation allowed)
__device__ __align__(16) float g_Yq [(size_t)ROWS_A * DQK_];
__device__ __align__(16) float g_Yk [(size_t)ROWS_B * DQK_];
__device__ __align__(16) float g_Yv [(size_t)ROWS_B * DV_];
__device__ __align__(16) float g_Ywv[(size_t)ROWS_A * DV_];
__device__ __align__(16) float g_Yf [(size_t)ROWS_A * DQ_];
__device__ __align__(16) float g_Bp  [(size_t)ROWS_B * KPAD];
__device__ __align__(16) float g_Wkvp[1024 * KPAD];   // Wk rows 0-511, Wv rows 512-1023
__device__ float g_stats[8 * 512];
__device__ float g_cnt[2];

// ---------------------------------------------------------------------------
// Helpers
// ---------------------------------------------------------------------------
__device__ __forceinline__ void split2(float x0, float x1, uint32_t& h, uint32_t& l) {
    uint32_t hp;
    asm("cvt.rn.bf16x2.f32 %0, %1, %2;" : "=r"(hp) : "f"(x1), "f"(x0));
    float h0 = __uint_as_float(hp << 16);
    float h1 = __uint_as_float(hp & 0xffff0000u);
    asm("cvt.rn.bf16x2.f32 %0, %1, %2;" : "=r"(l) : "f"(x1 - h1), "f"(x0 - h0));
    h = hp;
}

#define MMA_BF16(c, a, b)                                                  \
  asm volatile("mma.sync.aligned.m16n8k16.row.col.f32.bf16.bf16.f32 "      \
    "{%0,%1,%2,%3}, {%4,%5,%6,%7}, {%8,%9}, {%0,%1,%2,%3};"                \
    : "+f"(c[0]), "+f"(c[1]), "+f"(c[2]), "+f"(c[3])                       \
    : "r"(a[0]), "r"(a[1]), "r"(a[2]), "r"(a[3]), "r"(b[0]), "r"(b[1]))

#define CP_ASYNC16(smem_a, gptr) \
  asm volatile("cp.async.cg.shared.global [%0], [%1], 16;" :: "r"(smem_a), "l"(gptr))
#define CP_COMMIT() asm volatile("cp.async.commit_group;")
#define CP_WAIT0()  asm volatile("cp.async.wait_group 0;" ::: "memory")

// ---------------------------------------------------------------------------
// Fused init: zero stats + length sums. One block, 256 threads.
// ---------------------------------------------------------------------------
__global__ void init_kernel(const int* __restrict__ a_lens,
                            const int* __restrict__ b_lens) {
    int t = threadIdx.x;
    for (int i = t; i < 8 * 512; i += 256) g_stats[i] = 0.0f;

    __shared__ int sh[256];
    sh[t] = a_lens[t];
    __syncthreads();
    for (int o = 128; o; o >>= 1) { if (t < o) sh[t] += sh[t + o]; __syncthreads(); }
    if (t == 0) g_cnt[0] = (float)sh[0];
    __syncthreads();
    sh[t] = b_lens[t];
    __syncthreads();
    for (int o = 128; o; o >>= 1) { if (t < o) sh[t] += sh[t + o]; __syncthreads(); }
    if (t == 0) g_cnt[1] = (float)sh[0];
}

// ---------------------------------------------------------------------------
// Fused pad: B (valid rows only) -> Bp; Wk, Wv -> fused Wkvp.
// ---------------------------------------------------------------------------
__global__ void pad_all_kernel(const float* __restrict__ B,
                               const float* __restrict__ Wk,
                               const float* __restrict__ Wv,
                               const int* __restrict__ b_lens) {
    int bid = blockIdx.x;
    const float* src;
    float* dst;
    if (bid < ROWS_B) {
        int sidx = bid >> 9;
        if ((bid & 511) >= b_lens[sidx]) return;   // invalid row: Bp stays 0
        src = B + (size_t)bid * DKV_;
        dst = g_Bp + (size_t)bid * KPAD;
    } else if (bid < ROWS_B + 512) {
        int r = bid - ROWS_B;
        src = Wk + (size_t)r * DKV_;
        dst = g_Wkvp + (size_t)r * KPAD;
    } else {
        int r = bid - ROWS_B - 512;
        src = Wv + (size_t)r * DKV_;
        dst = g_Wkvp + (size_t)(r + 512) * KPAD;
    }
    for (int k = threadIdx.x; k < KPAD; k += blockDim.x)
        dst[k] = (k < DKV_) ? src[k] : 0.0f;
}

// ---------------------------------------------------------------------------
// Tensor-core GEMM: bf16 split, cp.async double buffer, one sync per k-iter,
// fused masked BN stats, invalid row-tile skip, dual-output (fused KV) mode.
// 256 threads = 8 warps (2m x 4n), warp tile 64x32, block tile 128x128.
// ---------------------------------------------------------------------------
#define TBK 16
#define TST 24

__global__ __launch_bounds__(256)
void gemm_tc(const float* __restrict__ X, const float* __restrict__ W,
             const float* __restrict__ bias, float* __restrict__ C,
             const float* __restrict__ bias2, float* __restrict__ C2,
             int M, int N, int K,
             const int* __restrict__ lens, int Lshift,
             float* __restrict__ sumOut, float* __restrict__ sqOut,
             float* __restrict__ sum2,  float* __restrict__ sq2) {
    __shared__ float Xs[2][128][TST];
    __shared__ float Ws[2][128][TST];

    size_t row0 = (size_t)blockIdx.y * 128;
    int Lm1 = (1 << Lshift) - 1;
    if (((int)(row0 & Lm1)) >= lens[row0 >> Lshift]) return;

    int tid  = threadIdx.x;
    int warp = tid >> 5, lane = tid & 31;
    int wm = warp >> 2;
    int wn = warp & 3;
    int g  = lane >> 2, tig = lane & 3;

    int wcol0 = blockIdx.x * 128;     // column in fused weight space
    int col0  = wcol0;
    const float* bias_ = bias;
    float* C_ = C;
    float* sum_ = sumOut;
    float* sq_  = sqOut;
    if (col0 >= N) {                   // second output set (fused KV mode)
        col0 -= N;
        bias_ = bias2; C_ = C2; sum_ = sum2; sq_ = sq2;
    }

    float c[4][4][4];
#pragma unroll
    for (int mt = 0; mt < 4; mt++)
#pragma unroll
        for (int nt = 0; nt < 4; nt++)
#pragma unroll
            for (int i = 0; i < 4; i++) c[mt][nt][i] = 0.0f;

    int xr = tid >> 1;
    int xk = (tid & 1) * 8;

    const float* Xp = X + (row0 + xr) * (size_t)K + xk;
    const float* Wp = W + (size_t)(wcol0 + xr) * K + xk;

    uint32_t sx[2] = { (uint32_t)__cvta_generic_to_shared(&Xs[0][xr][xk]),
                       (uint32_t)__cvta_generic_to_shared(&Xs[1][xr][xk]) };
    uint32_t sw[2] = { (uint32_t)__cvta_generic_to_shared(&Ws[0][xr][xk]),
                       (uint32_t)__cvta_generic_to_shared(&Ws[1][xr][xk]) };

    int nk = K / TBK;

    auto stage = [&](int i, int b) {
        int k0 = i * TBK;
        CP_ASYNC16(sx[b],      Xp + k0);
        CP_ASYNC16(sx[b] + 16, Xp + k0 + 4);
        CP_ASYNC16(sw[b],      Wp + k0);
        CP_ASYNC16(sw[b] + 16, Wp + k0 + 4);
        CP_COMMIT();
    };

    stage(0, 0);

    for (int i = 0; i < nk; i++) {
        int buf = i & 1;
        CP_WAIT0();
        __syncthreads();
        if (i + 1 < nk) stage(i + 1, buf ^ 1);

        uint32_t ah[4][4], al[4][4];
#pragma unroll
        for (int mt = 0; mt < 4; mt++) {
            int r = wm * 64 + mt * 16 + g;
            float2 p0 = *reinterpret_cast<const float2*>(&Xs[buf][r][2 * tig]);
            float2 p1 = *reinterpret_cast<const float2*>(&Xs[buf][r + 8][2 * tig]);
            float2 p2 = *reinterpret_cast<const float2*>(&Xs[buf][r][2 * tig + 8]);
            float2 p3 = *reinterpret_cast<const float2*>(&Xs[buf][r + 8][2 * tig + 8]);
            split2(p0.x, p0.y, ah[mt][0], al[mt][0]);
            split2(p1.x, p1.y, ah[mt][1], al[mt][1]);
            split2(p2.x, p2.y, ah[mt][2], al[mt][2]);
            split2(p3.x, p3.y, ah[mt][3], al[mt][3]);
        }
#pragma unroll
        for (int nt = 0; nt < 4; nt++) {
            int n = wn * 32 + nt * 8 + g;
            float2 q0 = *reinterpret_cast<const float2*>(&Ws[buf][n][2 * tig]);
            float2 q1 = *reinterpret_cast<const float2*>(&Ws[buf][n][2 * tig + 8]);
            uint32_t bh[2], bl[2];
            split2(q0.x, q0.y, bh[0], bl[0]);
            split2(q1.x, q1.y, bh[1], bl[1]);
#pragma unroll
            for (int mt = 0; mt < 4; mt++) {
                MMA_BF16(c[mt][nt], ah[mt], bh);
                MMA_BF16(c[mt][nt], ah[mt], bl);
                MMA_BF16(c[mt][nt], al[mt], bh);
            }
        }
    }

    float ssum[4][2], ssq[4][2];
#pragma unroll
    for (int nt = 0; nt < 4; nt++) {
        ssum[nt][0] = ssum[nt][1] = 0.0f;
        ssq[nt][0]  = ssq[nt][1]  = 0.0f;
    }

#pragma unroll
    for (int mt = 0; mt < 4; mt++) {
        size_t r0 = row0 + wm * 64 + mt * 16 + g;
        size_t r1 = r0 + 8;
        bool v0 = ((int)(r0 & Lm1)) < lens[r0 >> Lshift];
        bool v1 = ((int)(r1 & Lm1)) < lens[r1 >> Lshift];
#pragma unroll
        for (int nt = 0; nt < 4; nt++) {
            int cc = col0 + wn * 32 + nt * 8 + tig * 2;
            float b0 = bias_[cc], b1 = bias_[cc + 1];
            float y00 = c[mt][nt][0] + b0;
            float y01 = c[mt][nt][1] + b1;
            float y10 = c[mt][nt][2] + b0;
            float y11 = c[mt][nt][3] + b1;
            C_[r0 * N + cc]     = y00;
            C_[r0 * N + cc + 1] = y01;
            C_[r1 * N + cc]     = y10;
            C_[r1 * N + cc + 1] = y11;
            if (v0) {
                ssum[nt][0] += y00; ssq[nt][0] += y00 * y00;
                ssum[nt][1] += y01; ssq[nt][1] += y01 * y01;
            }
            if (v1) {
                ssum[nt][0] += y10; ssq[nt][0] += y10 * y10;
                ssum[nt][1] += y11; ssq[nt][1] += y11 * y11;
            }
        }
    }

#pragma unroll
    for (int o = 16; o >= 4; o >>= 1) {
#pragma unroll
        for (int nt = 0; nt < 4; nt++) {
#pragma unroll
            for (int j = 0; j < 2; j++) {
                ssum[nt][j] += __shfl_xor_sync(0xffffffffu, ssum[nt][j], o);
                ssq[nt][j]  += __shfl_xor_sync(0xffffffffu, ssq[nt][j],  o);
            }
        }
    }
    if (g == 0) {
#pragma unroll
        for (int nt = 0; nt < 4; nt++) {
            int cc = col0 + wn * 32 + nt * 8 + tig * 2;
#pragma unroll
            for (int j = 0; j < 2; j++) {
                atomicAdd(&sum_[cc + j], ssum[nt][j]);
                atomicAdd(&sq_[cc + j],  ssq[nt][j]);
            }
        }
    }
}

// ---------------------------------------------------------------------------
// BN apply + ReLU + optional L2 row-normalize + optional row mask.
// 256 threads, two rows per block; invalid rows skipped / zeroed.
// ---------------------------------------------------------------------------
__global__ __launch_bounds__(256)
void bn_apply_kernel(float* __restrict__ Y, int D,
                     const float* __restrict__ ssum, const float* __restrict__ ssq,
                     const float* __restrict__ cntp,
                     const float* __restrict__ gamma, const float* __restrict__ beta,
                     const int* __restrict__ lens, int L,
                     int normalize, int maskOut, float* __restrict__ out) {
    int t  = threadIdx.x;
    int tl = t & 127;
    int r  = blockIdx.x * 2 + (t >> 7);
    int sidx = r / L;
    bool valid = ((r - sidx * L) < lens[sidx]);
    float inv = 1.0f / (*cntp);
    int active = D >> 2;

    float z[4] = {0.0f, 0.0f, 0.0f, 0.0f};
    float ss = 0.0f;
    if (tl < active && valid) {
        int cc = tl * 4;
        float4 y = *reinterpret_cast<const float4*>(&Y[(size_t)r * D + cc]);
        float yv[4] = {y.x, y.y, y.z, y.w};
#pragma unroll
        for (int i = 0; i < 4; i++) {
            int ci = cc + i;
            float mean = ssum[ci] * inv;
            float var  = fmaxf(ssq[ci] * inv - mean * mean, 0.0f);
            float zz = (yv[i] - mean) * rsqrtf(var + 1e-5f) * gamma[ci] + beta[ci];
            zz = fmaxf(zz, 0.0f);
            z[i] = zz;
            ss += zz * zz;
        }
    }

    __shared__ float red[8];
#pragma unroll
    for (int o = 16; o; o >>= 1) ss += __shfl_xor_sync(0xffffffffu, ss, o);
    if ((t & 31) == 0) red[t >> 5] = ss;
    __syncthreads();
    int rg = (t >> 7) * 4;
    float tot = red[rg] + red[rg + 1] + red[rg + 2] + red[rg + 3];

    float scale = 1.0f;
    if (normalize) scale = 1.0f / fmaxf(sqrtf(tot), 1e-12f);

    if (tl < active) {
        float* dst = out ? out : Y;
        if (valid) {
            *reinterpret_cast<float4*>(&dst[(size_t)r * D + tl * 4]) =
                make_float4(z[0] * scale, z[1] * scale, z[2] * scale, z[3] * scale);
        } else if (maskOut) {
            *reinterpret_cast<float4*>(&dst[(size_t)r * D + tl * 4]) =
                make_float4(0.0f, 0.0f, 0.0f, 0.0f);
        }
    }
}

// ---------------------------------------------------------------------------
// Tensor-core attention (R12 config): 64 q-rows / block, 512 threads,
// 16 warps = 2m x 8n (warp 32x64), double-buffered cp.async staging,
// valid-length bounding.
// ---------------------------------------------------------------------------
#define AST 520
#define KBST 20
#define ATT_SMEM_FLOATS (64 * AST + 2 * 512 * KBST + 2 * 64 * KBST)
#define ATT_SMEM_BYTES  (ATT_SMEM_FLOATS * 4)   // 225280

__global__ __launch_bounds__(512)
void attention_tc(const float* __restrict__ q, const float* __restrict__ k,
                  const float* __restrict__ v, const int* __restrict__ b_lens,
                  const int* __restrict__ a_lens, float* __restrict__ wv) {
    int s   = blockIdx.x;
    int a0  = blockIdx.y * 64;
    if (a0 >= a_lens[s]) return;

    extern __shared__ float sm[];
    float* sS  = sm;
    float* sKb = sm + 64 * AST;
    float* sQb = sKb + 2 * 512 * KBST;

    int tid = threadIdx.x;
    int warp = tid >> 5, lane = tid & 31;
    int wm = warp >> 3;
    int wn = warp & 7;
    int g  = lane >> 2, tig = lane & 3;
    int nb = b_lens[s];
    int nb16 = (nb + 15) & ~15;
    int nbc  = nb16 >> 4;

    const float* qs = q + ((size_t)s * LA_ + a0) * DQK_;
    const float* ks = k + (size_t)s * LB_ * DQK_;
    const float* vs = v + (size_t)s * LB_ * DV_;

    uint32_t sKa[2] = { (uint32_t)__cvta_generic_to_shared(sKb),
                        (uint32_t)__cvta_generic_to_shared(sKb + 512 * KBST) };
    uint32_t sQa[2] = { (uint32_t)__cvta_generic_to_shared(sQb),
                        (uint32_t)__cvta_generic_to_shared(sQb + 64 * KBST) };

    float c[2][8][4];
#pragma unroll
    for (int mt = 0; mt < 2; mt++)
#pragma unroll
        for (int nt = 0; nt < 8; nt++)
#pragma unroll
            for (int i = 0; i < 4; i++) c[mt][nt][i] = 0.0f;

    auto stageA = [&](int ci, int b) {
        int d0 = ci * 16;
        if (tid < 256) {
            int r = tid >> 2, c4 = (tid & 3) * 4;
            CP_ASYNC16(sQa[b] + (r * KBST + c4) * 4,
                       qs + (size_t)r * DQK_ + d0 + c4);
        }
#pragma unroll
        for (int j = 0; j < 4; j++) {
            int idx = tid + 512 * j;
            int r = idx >> 2, c4 = (idx & 3) * 4;
            if (r < nb16)
                CP_ASYNC16(sKa[b] + (r * KBST + c4) * 4,
                           ks + (size_t)r * DQK_ + d0 + c4);
        }
        CP_COMMIT();
    };

    stageA(0, 0);

    for (int ci = 0; ci < 32; ci++) {
        int buf = ci & 1;
        CP_WAIT0();
        __syncthreads();
        if (ci + 1 < 32) stageA(ci + 1, buf ^ 1);

        const float* sQc = sQb + buf * 64 * KBST;
        const float* sKc = sKb + buf * 512 * KBST;

        uint32_t ah[2][4], al[2][4];
#pragma unroll
        for (int mt = 0; mt < 2; mt++) {
            int r = wm * 32 + mt * 16 + g;
            float2 p0 = *reinterpret_cast<const float2*>(&sQc[r * KBST + 2 * tig]);
            float2 p1 = *reinterpret_cast<const float2*>(&sQc[(r + 8) * KBST + 2 * tig]);
            float2 p2 = *reinterpret_cast<const float2*>(&sQc[r * KBST + 2 * tig + 8]);
            float2 p3 = *reinterpret_cast<const float2*>(&sQc[(r + 8) * KBST + 2 * tig + 8]);
            split2(p0.x, p0.y, ah[mt][0], al[mt][0]);
            split2(p1.x, p1.y, ah[mt][1], al[mt][1]);
            split2(p2.x, p2.y, ah[mt][2], al[mt][2]);
            split2(p3.x, p3.y, ah[mt][3], al[mt][3]);
        }
#pragma unroll
        for (int nt = 0; nt < 8; nt++) {
            int nbase = wn * 64 + nt * 8;
            if (nbase >= nb) continue;
            int n = nbase + g;
            float2 q0 = *reinterpret_cast<const float2*>(&sKc[n * KBST + 2 * tig]);
            float2 q1 = *reinterpret_cast<const float2*>(&sKc[n * KBST + 2 * tig + 8]);
            uint32_t bh[2], bl[2];
            split2(q0.x, q0.y, bh[0], bl[0]);
            split2(q1.x, q1.y, bh[1], bl[1]);
#pragma unroll
            for (int mt = 0; mt < 2; mt++) {
                MMA_BF16(c[mt][nt], ah[mt], bh);
                MMA_BF16(c[mt][nt], ah[mt], bl);
                MMA_BF16(c[mt][nt], al[mt], bh);
            }
        }
    }

    const float scaler = 6.25f;
#pragma unroll
    for (int mt = 0; mt < 2; mt++) {
        int r = wm * 32 + mt * 16 + g;
#pragma unroll
        for (int nt = 0; nt < 8; nt++) {
            int col = wn * 64 + nt * 8 + tig * 2;
            float v0 = c[mt][nt][0] * scaler;
            float v1 = c[mt][nt][1] * scaler;
            float v2 = c[mt][nt][2] * scaler;
            float v3 = c[mt][nt][3] * scaler;
            sS[r * AST + col]           = (col     < nb) ? v0 : -1e30f;
            sS[r * AST + col + 1]       = (col + 1 < nb) ? v1 : -1e30f;
            sS[(r + 8) * AST + col]     = (col     < nb) ? v2 : -1e30f;
            sS[(r + 8) * AST + col + 1] = (col + 1 < nb) ? v3 : -1e30f;
        }
    }
    __syncthreads();

#pragma unroll
    for (int rr = 0; rr < 4; rr++) {
        int row = warp * 4 + rr;
        float m = -1e30f;
        for (int cc = lane; cc < nb16; cc += 32) m = fmaxf(m, sS[row * AST + cc]);
#pragma unroll
        for (int o = 16; o; o >>= 1) m = fmaxf(m, __shfl_xor_sync(0xffffffffu, m, o));
        float sum = 0.0f;
        for (int cc = lane; cc < nb16; cc += 32) {
            float e = __expf(sS[row * AST + cc] - m);
            sS[row * AST + cc] = e;
            sum += e;
        }
#pragma unroll
        for (int o = 16; o; o >>= 1) sum += __shfl_xor_sync(0xffffffffu, sum, o);
        float invs = 1.0f / sum;
        for (int cc = lane; cc < nb16; cc += 32) sS[row * AST + cc] *= invs;
    }
    __syncthreads();

#pragma unroll
    for (int mt = 0; mt < 2; mt++)
#pragma unroll
        for (int nt = 0; nt < 8; nt++)
#pragma unroll
            for (int i = 0; i < 4; i++) c[mt][nt][i] = 0.0f;

    auto stageB = [&](int bi, int b) {
        float* dst = sKb + b * 512 * KBST;
        int b0 = bi * 16;
#pragma unroll
        for (int j = 0; j < 4; j++) {
            int idx = tid + 512 * j;
            int kk = idx & 15, dg = idx >> 4;
            float4 vv = *reinterpret_cast<const float4*>(
                &vs[(size_t)(b0 + kk) * DV_ + dg * 4]);
            dst[(dg * 4 + 0) * KBST + kk] = vv.x;
            dst[(dg * 4 + 1) * KBST + kk] = vv.y;
            dst[(dg * 4 + 2) * KBST + kk] = vv.z;
            dst[(dg * 4 + 3) * KBST + kk] = vv.w;
        }
    };

    stageB(0, 0);
    __syncthreads();

    for (int bi = 0; bi < nbc; bi++) {
        int buf = bi & 1;
        if (bi + 1 < nbc) stageB(bi + 1, buf ^ 1);

        int b0 = bi * 16;
        const float* sVc = sKb + buf * 512 * KBST;

        uint32_t ah[2][4], al[2][4];
#pragma unroll
        for (int mt = 0; mt < 2; mt++) {
            int r = wm * 32 + mt * 16 + g;
            float2 p0 = *reinterpret_cast<const float2*>(&sS[r * AST + b0 + 2 * tig]);
            float2 p1 = *reinterpret_cast<const float2*>(&sS[(r + 8) * AST + b0 + 2 * tig]);
            float2 p2 = *reinterpret_cast<const float2*>(&sS[r * AST + b0 + 2 * tig + 8]);
            float2 p3 = *reinterpret_cast<const float2*>(&sS[(r + 8) * AST + b0 + 2 * tig + 8]);
            split2(p0.x, p0.y, ah[mt][0], al[mt][0]);
            split2(p1.x, p1.y, ah[mt][1], al[mt][1]);
            split2(p2.x, p2.y, ah[mt][2], al[mt][2]);
            split2(p3.x, p3.y, ah[mt][3], al[mt][3]);
        }
#pragma unroll
        for (int nt = 0; nt < 8; nt++) {
            int n = wn * 64 + nt * 8 + g;
            float2 q0 = *reinterpret_cast<const float2*>(&sVc[n * KBST + 2 * tig]);
            float2 q1 = *reinterpret_cast<const float2*>(&sVc[n * KBST + 2 * tig + 8]);
            uint32_t bh[2], bl[2];
            split2(q0.x, q0.y, bh[0], bl[0]);
            split2(q1.x, q1.y, bh[1], bl[1]);
#pragma unroll
            for (int mt = 0; mt < 2; mt++) {
                MMA_BF16(c[mt][nt], ah[mt], bh);
                MMA_BF16(c[mt][nt], ah[mt], bl);
                MMA_BF16(c[mt][nt], al[mt], bh);
            }
        }
        __syncthreads();
    }

    float* wvp = wv + ((size_t)s * LA_ + a0) * DV_;
#pragma unroll
    for (int mt = 0; mt < 2; mt++) {
        int r = wm * 32 + mt * 16 + g;
#pragma unroll
        for (int nt = 0; nt < 8; nt++) {
            int col = wn * 64 + nt * 8 + tig * 2;
            wvp[(size_t)r * DV_ + col]           = c[mt][nt][0];
            wvp[(size_t)r * DV_ + col + 1]       = c[mt][nt][1];
            wvp[(size_t)(r + 8) * DV_ + col]     = c[mt][nt][2];
            wvp[(size_t)(r + 8) * DV_ + col + 1] = c[mt][nt][3];
        }
    }
}

// ---------------------------------------------------------------------------
// Launch
// ---------------------------------------------------------------------------
extern "C" void kernel_launch(void* const* d_in, const int* in_sizes, int n_in,
                              void* d_out, int out_size) {
    const float* A      = (const float*)d_in[0];
    const float* B      = (const float*)d_in[1];
    const int*   a_lens = (const int*)  d_in[2];
    const int*   b_lens = (const int*)  d_in[3];
    const float* Wq     = (const float*)d_in[4];
    const float* bq     = (const float*)d_in[5];
    const float* gq     = (const float*)d_in[6];
    const float* betaq  = (const float*)d_in[7];
    const float* Wk     = (const float*)d_in[8];
    const float* bk     = (const float*)d_in[9];
    const float* gk     = (const float*)d_in[10];
    const float* betak  = (const float*)d_in[11];
    const float* Wv     = (const float*)d_in[12];
    const float* bv     = (const float*)d_in[13];
    const float* gv     = (const float*)d_in[14];
    const float* betav  = (const float*)d_in[15];
    const float* Wf     = (const float*)d_in[16];
    const float* bf     = (const float*)d_in[17];
    const float* gf     = (const float*)d_in[18];
    const float* betaf  = (const float*)d_in[19];
    float* out = (float*)d_out;

    float *Yq, *Yk, *Yv, *Ywv, *Yf, *Bp, *Wkvp, *stats, *cnt;
    cudaGetSymbolAddress((void**)&Yq,   g_Yq);
    cudaGetSymbolAddress((void**)&Yk,   g_Yk);
    cudaGetSymbolAddress((void**)&Yv,   g_Yv);
    cudaGetSymbolAddress((void**)&Ywv,  g_Ywv);
    cudaGetSymbolAddress((void**)&Yf,   g_Yf);
    cudaGetSymbolAddress((void**)&Bp,   g_Bp);
    cudaGetSymbolAddress((void**)&Wkvp, g_Wkvp);
    cudaGetSymbolAddress((void**)&stats, g_stats);
    cudaGetSymbolAddress((void**)&cnt,  g_cnt);

    cudaFuncSetAttribute(attention_tc,
                         cudaFuncAttributeMaxDynamicSharedMemorySize, ATT_SMEM_BYTES);

    float* sum_q = stats + 0 * 512;
    float* sq_q  = stats + 1 * 512;
    float* sum_k = stats + 2 * 512;
    float* sq_k  = stats + 3 * 512;
    float* sum_v = stats + 4 * 512;
    float* sq_v  = stats + 5 * 512;
    float* sum_f = stats + 6 * 512;
    float* sq_f  = stats + 7 * 512;

    // 0) fused init + fused pad
    init_kernel<<<1, 256>>>(a_lens, b_lens);
    pad_all_kernel<<<ROWS_B + 1024, 128>>>(B, Wk, Wv, b_lens);

    // 1) Q projection + fused K/V projection
    gemm_tc<<<dim3(DQK_ / 128, ROWS_A / 128), 256>>>(A, Wq, bq, Yq, bq, Yq,
        ROWS_A, DQK_, DQ_, a_lens, 7, sum_q, sq_q, sum_q, sq_q);
    gemm_tc<<<dim3(8, ROWS_B / 128), 256>>>(Bp, Wkvp, bk, Yk, bv, Yv,
        ROWS_B, DQK_, KPAD, b_lens, 9, sum_k, sq_k, sum_v, sq_v);

    // 2) BN + ReLU + L2-normalize (in-place)
    bn_apply_kernel<<<ROWS_A / 2, 256>>>(Yq, DQK_, sum_q, sq_q, cnt + 0, gq, betaq,
                                         a_lens, LA_, 1, 0, nullptr);
    bn_apply_kernel<<<ROWS_B / 2, 256>>>(Yk, DQK_, sum_k, sq_k, cnt + 1, gk, betak,
                                         b_lens, LB_, 1, 0, nullptr);
    bn_apply_kernel<<<ROWS_B / 2, 256>>>(Yv, DV_,  sum_v, sq_v, cnt + 1, gv, betav,
                                         b_lens, LB_, 1, 0, nullptr);

    // 3) attention (64-row tiles, double-buffered staging)
    attention_tc<<<dim3(S_, LA_ / 64), 512, ATT_SMEM_BYTES>>>(
        Yq, Yk, Yv, b_lens, a_lens, Ywv);

    // 4) final projection + BN + ReLU + output mask
    gemm_tc<<<dim3(DQ_ / 128, ROWS_A / 128), 256>>>(Ywv, Wf, bf, Yf, bf, Yf,
        ROWS_A, DQ_, DV_, a_lens, 7, sum_f, sq_f, sum_f, sq_f);
    bn_apply_kernel<<<ROWS_A / 2, 256>>>(Yf, DQ_, sum_f, sq_f, cnt + 0, gf, betaf,
                                         a_lens, LA_, 0, 1, out);
}

// round 15
// speedup vs baseline: 1.0593x; 1.0078x over previous
#include <cuda_runtime.h>
#include <cuda_bf16.h>
#include <math.h>
#include <stdint.h>

// ---------------------------------------------------------------------------
// Problem constants
// ---------------------------------------------------------------------------
#define S_   256
#define LA_  128
#define LB_  512
#define DQ_  256
#define DKV_ 265
#define DQK_ 512
#define DV_  512
#define KPAD 272            // DKV_ padded to multiple of 16 (16B-aligned rows)

#define ROWS_A (S_ * LA_)   // 32768
#define ROWS_B (S_ * LB_)   // 131072

// Scratch (device globals; zero-initialized at load; no allocation allowed)
__device__ __align__(16) float g_Yq [(size_t)ROWS_A * DQK_];
__device__ __align__(16) float g_Yk [(size_t)ROWS_B * DQK_];
__device__ __align__(16) float g_Yv [(size_t)ROWS_B * DV_];
__device__ __align__(16) float g_Ywv[(size_t)ROWS_A * DV_];
__device__ __align__(16) float g_Yf [(size_t)ROWS_A * DQ_];
__device__ __align__(16) float g_Bp  [(size_t)ROWS_B * KPAD];
__device__ __align__(16) float g_Wkvp[1024 * KPAD];   // Wk rows 0-511, Wv rows 512-1023
__device__ float g_stats[8 * 512];
__device__ float g_cnt[2];

// ---------------------------------------------------------------------------
// Helpers
// ---------------------------------------------------------------------------
__device__ __forceinline__ void split2(float x0, float x1, uint32_t& h, uint32_t& l) {
    uint32_t hp;
    asm("cvt.rn.bf16x2.f32 %0, %1, %2;" : "=r"(hp) : "f"(x1), "f"(x0));
    float h0 = __uint_as_float(hp << 16);
    float h1 = __uint_as_float(hp & 0xffff0000u);
    asm("cvt.rn.bf16x2.f32 %0, %1, %2;" : "=r"(l) : "f"(x1 - h1), "f"(x0 - h0));
    h = hp;
}

#define MMA_BF16(c, a, b)                                                  \
  asm volatile("mma.sync.aligned.m16n8k16.row.col.f32.bf16.bf16.f32 "      \
    "{%0,%1,%2,%3}, {%4,%5,%6,%7}, {%8,%9}, {%0,%1,%2,%3};"                \
    : "+f"(c[0]), "+f"(c[1]), "+f"(c[2]), "+f"(c[3])                       \
    : "r"(a[0]), "r"(a[1]), "r"(a[2]), "r"(a[3]), "r"(b[0]), "r"(b[1]))

#define CP_ASYNC16(smem_a, gptr) \
  asm volatile("cp.async.cg.shared.global [%0], [%1], 16;" :: "r"(smem_a), "l"(gptr))
#define CP_COMMIT() asm volatile("cp.async.commit_group;")
#define CP_WAIT1()  asm volatile("cp.async.wait_group 1;" ::: "memory")
#define CP_WAIT0()  asm volatile("cp.async.wait_group 0;" ::: "memory")

// ---------------------------------------------------------------------------
// Fused init: zero stats + length sums. One block, 256 threads.
// ---------------------------------------------------------------------------
__global__ void init_kernel(const int* __restrict__ a_lens,
                            const int* __restrict__ b_lens) {
    int t = threadIdx.x;
    for (int i = t; i < 8 * 512; i += 256) g_stats[i] = 0.0f;

    __shared__ int sh[256];
    sh[t] = a_lens[t];
    __syncthreads();
    for (int o = 128; o; o >>= 1) { if (t < o) sh[t] += sh[t + o]; __syncthreads(); }
    if (t == 0) g_cnt[0] = (float)sh[0];
    __syncthreads();
    sh[t] = b_lens[t];
    __syncthreads();
    for (int o = 128; o; o >>= 1) { if (t < o) sh[t] += sh[t + o]; __syncthreads(); }
    if (t == 0) g_cnt[1] = (float)sh[0];
}

// ---------------------------------------------------------------------------
// Fused pad: B (valid rows only) -> Bp; Wk, Wv -> fused Wkvp.
// ---------------------------------------------------------------------------
__global__ void pad_all_kernel(const float* __restrict__ B,
                               const float* __restrict__ Wk,
                               const float* __restrict__ Wv,
                               const int* __restrict__ b_lens) {
    int bid = blockIdx.x;
    const float* src;
    float* dst;
    if (bid < ROWS_B) {
        int sidx = bid >> 9;
        if ((bid & 511) >= b_lens[sidx]) return;   // invalid row: Bp stays 0
        src = B + (size_t)bid * DKV_;
        dst = g_Bp + (size_t)bid * KPAD;
    } else if (bid < ROWS_B + 512) {
        int r = bid - ROWS_B;
        src = Wk + (size_t)r * DKV_;
        dst = g_Wkvp + (size_t)r * KPAD;
    } else {
        int r = bid - ROWS_B - 512;
        src = Wv + (size_t)r * DKV_;
        dst = g_Wkvp + (size_t)(r + 512) * KPAD;
    }
    for (int k = threadIdx.x; k < KPAD; k += blockDim.x)
        dst[k] = (k < DKV_) ? src[k] : 0.0f;
}

// ---------------------------------------------------------------------------
// Tensor-core GEMM: bf16 split, 3-stage cp.async pipeline (dynamic smem),
// one sync per k-iter, fused masked BN stats, invalid row-tile skip,
// dual-output (fused KV) mode.
// 256 threads = 8 warps (2m x 4n), warp tile 64x32, block tile 128x128.
// ---------------------------------------------------------------------------
#define TBK 16
#define TST 24
#define GEMM_BUF_FLOATS (128 * TST)                      // 3072 per array per stage
#define GEMM_SMEM_BYTES (3 * GEMM_BUF_FLOATS * 2 * 4)    // 73728

__global__ __launch_bounds__(256)
void gemm_tc(const float* __restrict__ X, const float* __restrict__ W,
             const float* __restrict__ bias, float* __restrict__ C,
             const float* __restrict__ bias2, float* __restrict__ C2,
             int M, int N, int K,
             const int* __restrict__ lens, int Lshift,
             float* __restrict__ sumOut, float* __restrict__ sqOut,
             float* __restrict__ sum2,  float* __restrict__ sq2) {
    extern __shared__ float smem[];
    float* Xs = smem;                        // 3 stages x [128][TST]
    float* Ws = smem + 3 * GEMM_BUF_FLOATS;  // 3 stages x [128][TST]

    size_t row0 = (size_t)blockIdx.y * 128;
    int Lm1 = (1 << Lshift) - 1;
    if (((int)(row0 & Lm1)) >= lens[row0 >> Lshift]) return;

    int tid  = threadIdx.x;
    int warp = tid >> 5, lane = tid & 31;
    int wm = warp >> 2;
    int wn = warp & 3;
    int g  = lane >> 2, tig = lane & 3;

    int wcol0 = blockIdx.x * 128;     // column in fused weight space
    int col0  = wcol0;
    const float* bias_ = bias;
    float* C_ = C;
    float* sum_ = sumOut;
    float* sq_  = sqOut;
    if (col0 >= N) {                   // second output set (fused KV mode)
        col0 -= N;
        bias_ = bias2; C_ = C2; sum_ = sum2; sq_ = sq2;
    }

    float c[4][4][4];
#pragma unroll
    for (int mt = 0; mt < 4; mt++)
#pragma unroll
        for (int nt = 0; nt < 4; nt++)
#pragma unroll
            for (int i = 0; i < 4; i++) c[mt][nt][i] = 0.0f;

    int xr = tid >> 1;
    int xk = (tid & 1) * 8;

    const float* Xp = X + (row0 + xr) * (size_t)K + xk;
    const float* Wp = W + (size_t)(wcol0 + xr) * K + xk;

    uint32_t sxb = (uint32_t)__cvta_generic_to_shared(&Xs[xr * TST + xk]);
    uint32_t swb = (uint32_t)__cvta_generic_to_shared(&Ws[xr * TST + xk]);

    int nk = K / TBK;

    auto stage = [&](int i, int b) {
        int k0 = i * TBK;
        uint32_t off = (uint32_t)(b * GEMM_BUF_FLOATS * 4);
        CP_ASYNC16(sxb + off,      Xp + k0);
        CP_ASYNC16(sxb + off + 16, Xp + k0 + 4);
        CP_ASYNC16(swb + off,      Wp + k0);
        CP_ASYNC16(swb + off + 16, Wp + k0 + 4);
        CP_COMMIT();
    };

    stage(0, 0);
    stage(1, 1);

    int bufi = 0;
    for (int i = 0; i < nk; i++) {
        if (i + 1 < nk) CP_WAIT1(); else CP_WAIT0();
        __syncthreads();
        if (i + 2 < nk) stage(i + 2, (bufi + 2) % 3);

        const float* Xc = Xs + bufi * GEMM_BUF_FLOATS;
        const float* Wc = Ws + bufi * GEMM_BUF_FLOATS;

        uint32_t ah[4][4], al[4][4];
#pragma unroll
        for (int mt = 0; mt < 4; mt++) {
            int r = wm * 64 + mt * 16 + g;
            float2 p0 = *reinterpret_cast<const float2*>(&Xc[r * TST + 2 * tig]);
            float2 p1 = *reinterpret_cast<const float2*>(&Xc[(r + 8) * TST + 2 * tig]);
            float2 p2 = *reinterpret_cast<const float2*>(&Xc[r * TST + 2 * tig + 8]);
            float2 p3 = *reinterpret_cast<const float2*>(&Xc[(r + 8) * TST + 2 * tig + 8]);
            split2(p0.x, p0.y, ah[mt][0], al[mt][0]);
            split2(p1.x, p1.y, ah[mt][1], al[mt][1]);
            split2(p2.x, p2.y, ah[mt][2], al[mt][2]);
            split2(p3.x, p3.y, ah[mt][3], al[mt][3]);
        }
#pragma unroll
        for (int nt = 0; nt < 4; nt++) {
            int n = wn * 32 + nt * 8 + g;
            float2 q0 = *reinterpret_cast<const float2*>(&Wc[n * TST + 2 * tig]);
            float2 q1 = *reinterpret_cast<const float2*>(&Wc[n * TST + 2 * tig + 8]);
            uint32_t bh[2], bl[2];
            split2(q0.x, q0.y, bh[0], bl[0]);
            split2(q1.x, q1.y, bh[1], bl[1]);
#pragma unroll
            for (int mt = 0; mt < 4; mt++) {
                MMA_BF16(c[mt][nt], ah[mt], bh);
                MMA_BF16(c[mt][nt], ah[mt], bl);
                MMA_BF16(c[mt][nt], al[mt], bh);
            }
        }
        bufi = (bufi + 1) % 3;
    }

    float ssum[4][2], ssq[4][2];
#pragma unroll
    for (int nt = 0; nt < 4; nt++) {
        ssum[nt][0] = ssum[nt][1] = 0.0f;
        ssq[nt][0]  = ssq[nt][1]  = 0.0f;
    }

#pragma unroll
    for (int mt = 0; mt < 4; mt++) {
        size_t r0 = row0 + wm * 64 + mt * 16 + g;
        size_t r1 = r0 + 8;
        bool v0 = ((int)(r0 & Lm1)) < lens[r0 >> Lshift];
        bool v1 = ((int)(r1 & Lm1)) < lens[r1 >> Lshift];
#pragma unroll
        for (int nt = 0; nt < 4; nt++) {
            int cc = col0 + wn * 32 + nt * 8 + tig * 2;
            float b0 = bias_[cc], b1 = bias_[cc + 1];
            float y00 = c[mt][nt][0] + b0;
            float y01 = c[mt][nt][1] + b1;
            float y10 = c[mt][nt][2] + b0;
            float y11 = c[mt][nt][3] + b1;
            C_[r0 * N + cc]     = y00;
            C_[r0 * N + cc + 1] = y01;
            C_[r1 * N + cc]     = y10;
            C_[r1 * N + cc + 1] = y11;
            if (v0) {
                ssum[nt][0] += y00; ssq[nt][0] += y00 * y00;
                ssum[nt][1] += y01; ssq[nt][1] += y01 * y01;
            }
            if (v1) {
                ssum[nt][0] += y10; ssq[nt][0] += y10 * y10;
                ssum[nt][1] += y11; ssq[nt][1] += y11 * y11;
            }
        }
    }

#pragma unroll
    for (int o = 16; o >= 4; o >>= 1) {
#pragma unroll
        for (int nt = 0; nt < 4; nt++) {
#pragma unroll
            for (int j = 0; j < 2; j++) {
                ssum[nt][j] += __shfl_xor_sync(0xffffffffu, ssum[nt][j], o);
                ssq[nt][j]  += __shfl_xor_sync(0xffffffffu, ssq[nt][j],  o);
            }
        }
    }
    if (g == 0) {
#pragma unroll
        for (int nt = 0; nt < 4; nt++) {
            int cc = col0 + wn * 32 + nt * 8 + tig * 2;
#pragma unroll
            for (int j = 0; j < 2; j++) {
                atomicAdd(&sum_[cc + j], ssum[nt][j]);
                atomicAdd(&sq_[cc + j],  ssq[nt][j]);
            }
        }
    }
}

// ---------------------------------------------------------------------------
// Fused BN apply for q/k/v (all D = 512): ReLU + L2 row-normalize, invalid
// rows skipped. 256 threads, two rows per block, per-block range dispatch.
// ---------------------------------------------------------------------------
__global__ __launch_bounds__(256)
void bn_qkv_kernel(float* __restrict__ Yq, float* __restrict__ Yk,
                   float* __restrict__ Yv,
                   const float* __restrict__ stats,
                   const float* __restrict__ cnt,
                   const float* __restrict__ gq, const float* __restrict__ betaq,
                   const float* __restrict__ gk, const float* __restrict__ betak,
                   const float* __restrict__ gv, const float* __restrict__ betav,
                   const int* __restrict__ a_lens, const int* __restrict__ b_lens) {
    int bid = blockIdx.x;
    float* Y;
    const float *ssum, *ssq, *gamma, *beta;
    const int* lens;
    int Lshift, r;
    float inv;
    if (bid < ROWS_A / 2) {
        Y = Yq; ssum = stats + 0 * 512; ssq = stats + 1 * 512;
        gamma = gq; beta = betaq; lens = a_lens; Lshift = 7;
        r = bid * 2; inv = 1.0f / cnt[0];
    } else if (bid < ROWS_A / 2 + ROWS_B / 2) {
        Y = Yk; ssum = stats + 2 * 512; ssq = stats + 3 * 512;
        gamma = gk; beta = betak; lens = b_lens; Lshift = 9;
        r = (bid - ROWS_A / 2) * 2; inv = 1.0f / cnt[1];
    } else {
        Y = Yv; ssum = stats + 4 * 512; ssq = stats + 5 * 512;
        gamma = gv; beta = betav; lens = b_lens; Lshift = 9;
        r = (bid - ROWS_A / 2 - ROWS_B / 2) * 2; inv = 1.0f / cnt[1];
    }

    int t  = threadIdx.x;
    int tl = t & 127;
    r += (t >> 7);
    bool valid = ((r & ((1 << Lshift) - 1)) < lens[r >> Lshift]);

    float z[4] = {0.0f, 0.0f, 0.0f, 0.0f};
    float ss = 0.0f;
    if (valid) {
        int cc = tl * 4;
        float4 y = *reinterpret_cast<const float4*>(&Y[(size_t)r * 512 + cc]);
        float yv4[4] = {y.x, y.y, y.z, y.w};
#pragma unroll
        for (int i = 0; i < 4; i++) {
            int ci = cc + i;
            float mean = ssum[ci] * inv;
            float var  = fmaxf(ssq[ci] * inv - mean * mean, 0.0f);
            float zz = (yv4[i] - mean) * rsqrtf(var + 1e-5f) * gamma[ci] + beta[ci];
            zz = fmaxf(zz, 0.0f);
            z[i] = zz;
            ss += zz * zz;
        }
    }

    __shared__ float red[8];
#pragma unroll
    for (int o = 16; o; o >>= 1) ss += __shfl_xor_sync(0xffffffffu, ss, o);
    if ((t & 31) == 0) red[t >> 5] = ss;
    __syncthreads();
    int rg = (t >> 7) * 4;
    float tot = red[rg] + red[rg + 1] + red[rg + 2] + red[rg + 3];
    float scale = 1.0f / fmaxf(sqrtf(tot), 1e-12f);

    if (valid) {
        *reinterpret_cast<float4*>(&Y[(size_t)r * 512 + tl * 4]) =
            make_float4(z[0] * scale, z[1] * scale, z[2] * scale, z[3] * scale);
    }
}

// ---------------------------------------------------------------------------
// Final BN apply (D=256): ReLU + output row mask (explicit zeros).
// ---------------------------------------------------------------------------
__global__ __launch_bounds__(256)
void bn_final_kernel(const float* __restrict__ Y,
                     const float* __restrict__ ssum, const float* __restrict__ ssq,
                     const float* __restrict__ cntp,
                     const float* __restrict__ gamma, const float* __restrict__ beta,
                     const int* __restrict__ lens, float* __restrict__ out) {
    int t  = threadIdx.x;
    int tl = t & 127;
    int r  = blockIdx.x * 2 + (t >> 7);
    bool valid = ((r & 127) < lens[r >> 7]);
    float inv = 1.0f / (*cntp);

    if (tl < 64) {
        int cc = tl * 4;
        float4 o4 = make_float4(0.0f, 0.0f, 0.0f, 0.0f);
        if (valid) {
            float4 y = *reinterpret_cast<const float4*>(&Y[(size_t)r * 256 + cc]);
            float yv4[4] = {y.x, y.y, y.z, y.w};
            float z[4];
#pragma unroll
            for (int i = 0; i < 4; i++) {
                int ci = cc + i;
                float mean = ssum[ci] * inv;
                float var  = fmaxf(ssq[ci] * inv - mean * mean, 0.0f);
                z[i] = fmaxf((yv4[i] - mean) * rsqrtf(var + 1e-5f) * gamma[ci] + beta[ci], 0.0f);
            }
            o4 = make_float4(z[0], z[1], z[2], z[3]);
        }
        *reinterpret_cast<float4*>(&out[(size_t)r * 256 + cc]) = o4;
    }
}

// ---------------------------------------------------------------------------
// Tensor-core attention (R12 config): 64 q-rows / block, 512 threads,
// 16 warps = 2m x 8n (warp 32x64), double-buffered cp.async staging,
// valid-length bounding.
// ---------------------------------------------------------------------------
#define AST 520
#define KBST 20
#define ATT_SMEM_FLOATS (64 * AST + 2 * 512 * KBST + 2 * 64 * KBST)
#define ATT_SMEM_BYTES  (ATT_SMEM_FLOATS * 4)   // 225280

__global__ __launch_bounds__(512)
void attention_tc(const float* __restrict__ q, const float* __restrict__ k,
                  const float* __restrict__ v, const int* __restrict__ b_lens,
                  const int* __restrict__ a_lens, float* __restrict__ wv) {
    int s   = blockIdx.x;
    int a0  = blockIdx.y * 64;
    if (a0 >= a_lens[s]) return;

    extern __shared__ float sm[];
    float* sS  = sm;
    float* sKb = sm + 64 * AST;
    float* sQb = sKb + 2 * 512 * KBST;

    int tid = threadIdx.x;
    int warp = tid >> 5, lane = tid & 31;
    int wm = warp >> 3;
    int wn = warp & 7;
    int g  = lane >> 2, tig = lane & 3;
    int nb = b_lens[s];
    int nb16 = (nb + 15) & ~15;
    int nbc  = nb16 >> 4;

    const float* qs = q + ((size_t)s * LA_ + a0) * DQK_;
    const float* ks = k + (size_t)s * LB_ * DQK_;
    const float* vs = v + (size_t)s * LB_ * DV_;

    uint32_t sKa[2] = { (uint32_t)__cvta_generic_to_shared(sKb),
                        (uint32_t)__cvta_generic_to_shared(sKb + 512 * KBST) };
    uint32_t sQa[2] = { (uint32_t)__cvta_generic_to_shared(sQb),
                        (uint32_t)__cvta_generic_to_shared(sQb + 64 * KBST) };

    float c[2][8][4];
#pragma unroll
    for (int mt = 0; mt < 2; mt++)
#pragma unroll
        for (int nt = 0; nt < 8; nt++)
#pragma unroll
            for (int i = 0; i < 4; i++) c[mt][nt][i] = 0.0f;

    auto stageA = [&](int ci, int b) {
        int d0 = ci * 16;
        if (tid < 256) {
            int r = tid >> 2, c4 = (tid & 3) * 4;
            CP_ASYNC16(sQa[b] + (r * KBST + c4) * 4,
                       qs + (size_t)r * DQK_ + d0 + c4);
        }
#pragma unroll
        for (int j = 0; j < 4; j++) {
            int idx = tid + 512 * j;
            int r = idx >> 2, c4 = (idx & 3) * 4;
            if (r < nb16)
                CP_ASYNC16(sKa[b] + (r * KBST + c4) * 4,
                           ks + (size_t)r * DQK_ + d0 + c4);
        }
        CP_COMMIT();
    };

    stageA(0, 0);

    for (int ci = 0; ci < 32; ci++) {
        int buf = ci & 1;
        CP_WAIT0();
        __syncthreads();
        if (ci + 1 < 32) stageA(ci + 1, buf ^ 1);

        const float* sQc = sQb + buf * 64 * KBST;
        const float* sKc = sKb + buf * 512 * KBST;

        uint32_t ah[2][4], al[2][4];
#pragma unroll
        for (int mt = 0; mt < 2; mt++) {
            int r = wm * 32 + mt * 16 + g;
            float2 p0 = *reinterpret_cast<const float2*>(&sQc[r * KBST + 2 * tig]);
            float2 p1 = *reinterpret_cast<const float2*>(&sQc[(r + 8) * KBST + 2 * tig]);
            float2 p2 = *reinterpret_cast<const float2*>(&sQc[r * KBST + 2 * tig + 8]);
            float2 p3 = *reinterpret_cast<const float2*>(&sQc[(r + 8) * KBST + 2 * tig + 8]);
            split2(p0.x, p0.y, ah[mt][0], al[mt][0]);
            split2(p1.x, p1.y, ah[mt][1], al[mt][1]);
            split2(p2.x, p2.y, ah[mt][2], al[mt][2]);
            split2(p3.x, p3.y, ah[mt][3], al[mt][3]);
        }
#pragma unroll
        for (int nt = 0; nt < 8; nt++) {
            int nbase = wn * 64 + nt * 8;
            if (nbase >= nb) continue;
            int n = nbase + g;
            float2 q0 = *reinterpret_cast<const float2*>(&sKc[n * KBST + 2 * tig]);
            float2 q1 = *reinterpret_cast<const float2*>(&sKc[n * KBST + 2 * tig + 8]);
            uint32_t bh[2], bl[2];
            split2(q0.x, q0.y, bh[0], bl[0]);
            split2(q1.x, q1.y, bh[1], bl[1]);
#pragma unroll
            for (int mt = 0; mt < 2; mt++) {
                MMA_BF16(c[mt][nt], ah[mt], bh);
                MMA_BF16(c[mt][nt], ah[mt], bl);
                MMA_BF16(c[mt][nt], al[mt], bh);
            }
        }
    }

    const float scaler = 6.25f;
#pragma unroll
    for (int mt = 0; mt < 2; mt++) {
        int r = wm * 32 + mt * 16 + g;
#pragma unroll
        for (int nt = 0; nt < 8; nt++) {
            int col = wn * 64 + nt * 8 + tig * 2;
            float v0 = c[mt][nt][0] * scaler;
            float v1 = c[mt][nt][1] * scaler;
            float v2 = c[mt][nt][2] * scaler;
            float v3 = c[mt][nt][3] * scaler;
            sS[r * AST + col]           = (col     < nb) ? v0 : -1e30f;
            sS[r * AST + col + 1]       = (col + 1 < nb) ? v1 : -1e30f;
            sS[(r + 8) * AST + col]     = (col     < nb) ? v2 : -1e30f;
            sS[(r + 8) * AST + col + 1] = (col + 1 < nb) ? v3 : -1e30f;
        }
    }
    __syncthreads();

#pragma unroll
    for (int rr = 0; rr < 4; rr++) {
        int row = warp * 4 + rr;
        float m = -1e30f;
        for (int cc = lane; cc < nb16; cc += 32) m = fmaxf(m, sS[row * AST + cc]);
#pragma unroll
        for (int o = 16; o; o >>= 1) m = fmaxf(m, __shfl_xor_sync(0xffffffffu, m, o));
        float sum = 0.0f;
        for (int cc = lane; cc < nb16; cc += 32) {
            float e = __expf(sS[row * AST + cc] - m);
            sS[row * AST + cc] = e;
            sum += e;
        }
#pragma unroll
        for (int o = 16; o; o >>= 1) sum += __shfl_xor_sync(0xffffffffu, sum, o);
        float invs = 1.0f / sum;
        for (int cc = lane; cc < nb16; cc += 32) sS[row * AST + cc] *= invs;
    }
    __syncthreads();

#pragma unroll
    for (int mt = 0; mt < 2; mt++)
#pragma unroll
        for (int nt = 0; nt < 8; nt++)
#pragma unroll
            for (int i = 0; i < 4; i++) c[mt][nt][i] = 0.0f;

    auto stageB = [&](int bi, int b) {
        float* dst = sKb + b * 512 * KBST;
        int b0 = bi * 16;
#pragma unroll
        for (int j = 0; j < 4; j++) {
            int idx = tid + 512 * j;
            int kk = idx & 15, dg = idx >> 4;
            float4 vv = *reinterpret_cast<const float4*>(
                &vs[(size_t)(b0 + kk) * DV_ + dg * 4]);
            dst[(dg * 4 + 0) * KBST + kk] = vv.x;
            dst[(dg * 4 + 1) * KBST + kk] = vv.y;
            dst[(dg * 4 + 2) * KBST + kk] = vv.z;
            dst[(dg * 4 + 3) * KBST + kk] = vv.w;
        }
    };

    stageB(0, 0);
    __syncthreads();

    for (int bi = 0; bi < nbc; bi++) {
        int buf = bi & 1;
        if (bi + 1 < nbc) stageB(bi + 1, buf ^ 1);

        int b0 = bi * 16;
        const float* sVc = sKb + buf * 512 * KBST;

        uint32_t ah[2][4], al[2][4];
#pragma unroll
        for (int mt = 0; mt < 2; mt++) {
            int r = wm * 32 + mt * 16 + g;
            float2 p0 = *reinterpret_cast<const float2*>(&sS[r * AST + b0 + 2 * tig]);
            float2 p1 = *reinterpret_cast<const float2*>(&sS[(r + 8) * AST + b0 + 2 * tig]);
            float2 p2 = *reinterpret_cast<const float2*>(&sS[r * AST + b0 + 2 * tig + 8]);
            float2 p3 = *reinterpret_cast<const float2*>(&sS[(r + 8) * AST + b0 + 2 * tig + 8]);
            split2(p0.x, p0.y, ah[mt][0], al[mt][0]);
            split2(p1.x, p1.y, ah[mt][1], al[mt][1]);
            split2(p2.x, p2.y, ah[mt][2], al[mt][2]);
            split2(p3.x, p3.y, ah[mt][3], al[mt][3]);
        }
#pragma unroll
        for (int nt = 0; nt < 8; nt++) {
            int n = wn * 64 + nt * 8 + g;
            float2 q0 = *reinterpret_cast<const float2*>(&sVc[n * KBST + 2 * tig]);
            float2 q1 = *reinterpret_cast<const float2*>(&sVc[n * KBST + 2 * tig + 8]);
            uint32_t bh[2], bl[2];
            split2(q0.x, q0.y, bh[0], bl[0]);
            split2(q1.x, q1.y, bh[1], bl[1]);
#pragma unroll
            for (int mt = 0; mt < 2; mt++) {
                MMA_BF16(c[mt][nt], ah[mt], bh);
                MMA_BF16(c[mt][nt], ah[mt], bl);
                MMA_BF16(c[mt][nt], al[mt], bh);
            }
        }
        __syncthreads();
    }

    float* wvp = wv + ((size_t)s * LA_ + a0) * DV_;
#pragma unroll
    for (int mt = 0; mt < 2; mt++) {
        int r = wm * 32 + mt * 16 + g;
#pragma unroll
        for (int nt = 0; nt < 8; nt++) {
            int col = wn * 64 + nt * 8 + tig * 2;
            wvp[(size_t)r * DV_ + col]           = c[mt][nt][0];
            wvp[(size_t)r * DV_ + col + 1]       = c[mt][nt][1];
            wvp[(size_t)(r + 8) * DV_ + col]     = c[mt][nt][2];
            wvp[(size_t)(r + 8) * DV_ + col + 1] = c[mt][nt][3];
        }
    }
}

// ---------------------------------------------------------------------------
// Launch
// ---------------------------------------------------------------------------
extern "C" void kernel_launch(void* const* d_in, const int* in_sizes, int n_in,
                              void* d_out, int out_size) {
    const float* A      = (const float*)d_in[0];
    const float* B      = (const float*)d_in[1];
    const int*   a_lens = (const int*)  d_in[2];
    const int*   b_lens = (const int*)  d_in[3];
    const float* Wq     = (const float*)d_in[4];
    const float* bq     = (const float*)d_in[5];
    const float* gq     = (const float*)d_in[6];
    const float* betaq  = (const float*)d_in[7];
    const float* Wk     = (const float*)d_in[8];
    const float* bk     = (const float*)d_in[9];
    const float* gk     = (const float*)d_in[10];
    const float* betak  = (const float*)d_in[11];
    const float* Wv     = (const float*)d_in[12];
    const float* bv     = (const float*)d_in[13];
    const float* gv     = (const float*)d_in[14];
    const float* betav  = (const float*)d_in[15];
    const float* Wf     = (const float*)d_in[16];
    const float* bf     = (const float*)d_in[17];
    const float* gf     = (const float*)d_in[18];
    const float* betaf  = (const float*)d_in[19];
    float* out = (float*)d_out;

    float *Yq, *Yk, *Yv, *Ywv, *Yf, *Bp, *Wkvp, *stats, *cnt;
    cudaGetSymbolAddress((void**)&Yq,   g_Yq);
    cudaGetSymbolAddress((void**)&Yk,   g_Yk);
    cudaGetSymbolAddress((void**)&Yv,   g_Yv);
    cudaGetSymbolAddress((void**)&Ywv,  g_Ywv);
    cudaGetSymbolAddress((void**)&Yf,   g_Yf);
    cudaGetSymbolAddress((void**)&Bp,   g_Bp);
    cudaGetSymbolAddress((void**)&Wkvp, g_Wkvp);
    cudaGetSymbolAddress((void**)&stats, g_stats);
    cudaGetSymbolAddress((void**)&cnt,  g_cnt);

    cudaFuncSetAttribute(attention_tc,
                         cudaFuncAttributeMaxDynamicSharedMemorySize, ATT_SMEM_BYTES);
    cudaFuncSetAttribute(gemm_tc,
                         cudaFuncAttributeMaxDynamicSharedMemorySize, GEMM_SMEM_BYTES);

    float* sum_q = stats + 0 * 512;
    float* sq_q  = stats + 1 * 512;
    float* sum_k = stats + 2 * 512;
    float* sq_k  = stats + 3 * 512;
    float* sum_v = stats + 4 * 512;
    float* sq_v  = stats + 5 * 512;
    float* sum_f = stats + 6 * 512;
    float* sq_f  = stats + 7 * 512;

    // 0) fused init + fused pad
    init_kernel<<<1, 256>>>(a_lens, b_lens);
    pad_all_kernel<<<ROWS_B + 1024, 128>>>(B, Wk, Wv, b_lens);

    // 1) Q projection + fused K/V projection (3-stage pipeline)
    gemm_tc<<<dim3(DQK_ / 128, ROWS_A / 128), 256, GEMM_SMEM_BYTES>>>(
        A, Wq, bq, Yq, bq, Yq, ROWS_A, DQK_, DQ_, a_lens, 7,
        sum_q, sq_q, sum_q, sq_q);
    gemm_tc<<<dim3(8, ROWS_B / 128), 256, GEMM_SMEM_BYTES>>>(
        Bp, Wkvp, bk, Yk, bv, Yv, ROWS_B, DQK_, KPAD, b_lens, 9,
        sum_k, sq_k, sum_v, sq_v);

    // 2) fused BN + ReLU + L2-normalize for q/k/v (one launch)
    bn_qkv_kernel<<<(ROWS_A + 2 * ROWS_B) / 2, 256>>>(
        Yq, Yk, Yv, stats, cnt, gq, betaq, gk, betak, gv, betav, a_lens, b_lens);

    // 3) attention (64-row tiles, double-buffered staging)
    attention_tc<<<dim3(S_, LA_ / 64), 512, ATT_SMEM_BYTES>>>(
        Yq, Yk, Yv, b_lens, a_lens, Ywv);

    // 4) final projection + BN + ReLU + output mask
    gemm_tc<<<dim3(DQ_ / 128, ROWS_A / 128), 256, GEMM_SMEM_BYTES>>>(
        Ywv, Wf, bf, Yf, bf, Yf, ROWS_A, DQ_, DV_, a_lens, 7,
        sum_f, sq_f, sum_f, sq_f);
    bn_final_kernel<<<ROWS_A / 2, 256>>>(Yf, sum_f, sq_f, cnt + 0, gf, betaf,
                                         a_lens, out);
}